// round 15
// baseline (speedup 1.0000x reference)
#include <cuda_runtime.h>
#include <math_constants.h>

// Static shape: N=65536, 16 segments of SEG=4096, D=3, K=20.
// T=2 split: each query handled by 2 threads; both halves share one
// 2048-point smem tile (split down the middle), fixing R14's LDG-latency
// regression while keeping the doubled warp parallelism.
#define KNN 20
#define NPTS 65536
#define SEG 4096
#define TILE 2048
#define HTILE 1024      // per-half slice of a tile
#define QPB 64          // queries per block
#define BLOCK 128       // QPB * 2
#define BUFCAP 8
#define NPH 13

typedef unsigned long long u64;

__device__ __forceinline__ u64 pk2(float lo, float hi) {
    u64 r;
    asm("mov.b64 %0, {%1, %2};" : "=l"(r) : "f"(lo), "f"(hi));
    return r;
}
__device__ __forceinline__ void upk2(float& lo, float& hi, u64 v) {
    asm("mov.b64 {%0, %1}, %2;" : "=f"(lo), "=f"(hi) : "l"(v));
}
__device__ __forceinline__ u64 add2(u64 a, u64 b) {
    u64 r;
    asm("add.rn.f32x2 %0, %1, %2;" : "=l"(r) : "l"(a), "l"(b));
    return r;
}
__device__ __forceinline__ u64 mul2(u64 a, u64 b) {
    u64 r;
    asm("mul.rn.f32x2 %0, %1, %2;" : "=l"(r) : "l"(a), "l"(b));
    return r;
}
__device__ __forceinline__ u64 fma2(u64 a, u64 b, u64 c) {
    u64 r;
    asm("fma.rn.f32x2 %0, %1, %2, %3;" : "=l"(r) : "l"(a), "l"(b), "l"(c));
    return r;
}

// Parallel predicated-shift insert into sorted ascending top-K.
// Strict '<' + ascending-j visit order = lax.top_k tie-breaking.
__device__ __forceinline__ void par_insert(float d, int j, float* dist,
                                           int* idx) {
    if (d < dist[KNN - 1]) {
        bool c[KNN];
#pragma unroll
        for (int k = 0; k < KNN; ++k) c[k] = d < dist[k];
#pragma unroll
        for (int k = KNN - 1; k > 0; --k) {
            dist[k] = c[k - 1] ? dist[k - 1] : (c[k] ? d : dist[k]);
            idx[k] = c[k - 1] ? idx[k - 1] : (c[k] ? j : idx[k]);
        }
        if (c[0]) {
            dist[0] = d;
            idx[0] = j;
        }
    }
}

__global__ __launch_bounds__(BLOCK, 7) void knn_kernel(
    const float* __restrict__ x, float* __restrict__ out) {
    // Layout (32 KB):
    //  scan phase:  [0,24K) tile xs/ys/zs (2048 each), [24K,32K) push buffer
    //  merge phase: [0,20K) per-thread sorted lists (reused after sync)
    __shared__ char smem_raw[32768];
    float* xs = (float*)smem_raw;
    float* ys = xs + TILE;
    float* zs = ys + TILE;
    float2* pbuf = (float2*)(smem_raw + 24576);   // [BUFCAP * BLOCK]
    float2* stage = (float2*)smem_raw;            // [BLOCK * KNN] (merge)

    const int tid = threadIdx.x;
    const int q = tid & (QPB - 1);        // query slot in block
    const int half = tid >> 6;            // 0 or 1
    const int blocksPerSeg = SEG / QPB;   // 64
    const int seg = blockIdx.x / blocksPerSeg;
    const int base = seg * SEG;
    const int qg = base + (blockIdx.x % blocksPerSeg) * QPB + q;

    // Key: d_j = xj*(xj+m2x)+yj*(yj+m2y)+zj*(zj+m2z) = |pj|^2 - 2 q.pj
    const float m2x = -2.0f * x[qg * 3 + 0];
    const float m2y = -2.0f * x[qg * 3 + 1];
    const float m2z = -2.0f * x[qg * 3 + 2];
    const u64 m2x2 = pk2(m2x, m2x);
    const u64 m2y2 = pk2(m2y, m2y);
    const u64 m2z2 = pk2(m2z, m2z);

    float dist[KNN];
    int idx[KNN];
#pragma unroll
    for (int k = 0; k < KNN; ++k) {
        dist[k] = CUDART_INF_F;
        idx[k] = 0;
    }

    float thr = CUDART_INF_F;
    int cnt = 0;

    // Load tile 0 (segment points [0, 2048)).
    for (int i = tid; i < TILE; i += BLOCK) {
        int g = (base + i) * 3;
        xs[i] = x[g + 0];
        ys[i] = x[g + 1];
        zs[i] = x[g + 2];
    }
    __syncthreads();

    const float4* __restrict__ xs4 = (const float4*)xs;
    const float4* __restrict__ ys4 = (const float4*)ys;
    const float4* __restrict__ zs4 = (const float4*)zs;
    const int hoff4 = half * (HTILE / 4);  // per-half float4 offset in tile

#define PUSH(dv, jv)                                                         \
    do {                                                                     \
        if ((dv) < thr) {                                                    \
            if (cnt < BUFCAP) {                                              \
                pbuf[cnt * BLOCK + tid] =                                    \
                    make_float2((dv), __int_as_float(jv));                   \
                cnt++;                                                       \
            } else {                                                         \
                par_insert((dv), (jv), dist, idx);                           \
            }                                                                \
        }                                                                    \
    } while (0)

    // Drain schedule over this thread's 2048-candidate sub-scan.
    // s==1024 phase boundary coincides with the tile switch.
    constexpr int B[NPH + 1] = {0,   20,  32,  48,   72,   108,  164,
                                248, 372, 560, 840,  1024, 1536, 2048};

#pragma unroll
    for (int ph = 0; ph < NPH; ++ph) {
        const int s = B[ph], e = B[ph + 1];
        int jbase;  // global j of this thread's local candidate s
        if (s < HTILE) {
            jbase = half * HTILE;       // tile 0: j = h*1024 + t
        } else {
            jbase = TILE + half * HTILE - HTILE;  // tile 1: j = 2048 + h*1024 + (t-1024)
        }
        if (s == HTILE) {  // switch to tile 1 (segment points [2048, 4096))
            __syncthreads();
            for (int i = tid; i < TILE; i += BLOCK) {
                int g = (base + TILE + i) * 3;
                xs[i] = x[g + 0];
                ys[i] = x[g + 1];
                zs[i] = x[g + 2];
            }
            __syncthreads();
        }
        const int t4base = (s < HTILE) ? 0 : (HTILE / 4);

#pragma unroll 2
        for (int t4 = s / 4; t4 < e / 4; ++t4) {
            const int i4 = hoff4 + (t4 - t4base);
            float4 vx = xs4[i4];
            float4 vy = ys4[i4];
            float4 vz = zs4[i4];
            const int j = jbase + (t4 - t4base) * 4 - (s < HTILE ? 0 : 0) +
                          (s < HTILE ? 0 : 0);
            const int jj = (s < HTILE) ? (half * HTILE + t4 * 4)
                                       : (TILE + half * HTILE + (t4 * 4 - HTILE));
            (void)j;

            u64 vx01 = pk2(vx.x, vx.y), vx23 = pk2(vx.z, vx.w);
            u64 vy01 = pk2(vy.x, vy.y), vy23 = pk2(vy.z, vy.w);
            u64 vz01 = pk2(vz.x, vz.y), vz23 = pk2(vz.z, vz.w);

            u64 acc01 = mul2(vx01, add2(vx01, m2x2));
            acc01 = fma2(vy01, add2(vy01, m2y2), acc01);
            acc01 = fma2(vz01, add2(vz01, m2z2), acc01);
            u64 acc23 = mul2(vx23, add2(vx23, m2x2));
            acc23 = fma2(vy23, add2(vy23, m2y2), acc23);
            acc23 = fma2(vz23, add2(vz23, m2z2), acc23);

            float d0, d1, d2, d3;
            upk2(d0, d1, acc01);
            upk2(d2, d3, acc23);

            PUSH(d0, jj + 0);
            PUSH(d1, jj + 1);
            PUSH(d2, jj + 2);
            PUSH(d3, jj + 3);
        }

        // Drain buffered items in push (= ascending j) order.
        int mx = __reduce_max_sync(0xffffffffu, cnt);
        for (int t = 0; t < mx; ++t) {
            if (t < cnt) {
                float2 en = pbuf[t * BLOCK + tid];
                par_insert(en.x, __float_as_int(en.y), dist, idx);
            }
        }
        cnt = 0;
        thr = dist[KNN - 1];
    }
#undef PUSH

    // ---- merge the two half-lists of each query ----
    __syncthreads();  // done with tile + push buffer; reuse as staging
#pragma unroll
    for (int k = 0; k < KNN; ++k)
        stage[tid * KNN + k] = make_float2(dist[k], __int_as_float(idx[k]));
    __syncthreads();

    if (half == 0) {
        const float2* la = &stage[tid * KNN];
        const float2* lb = &stage[(tid + QPB) * KNN];
        int ia = 0, ib = 0;
        float* o = out + (size_t)qg * KNN;
#pragma unroll
        for (int k = 0; k < KNN; ++k) {
            float2 ea = la[ia], eb = lb[ib];
            int ja = __float_as_int(ea.y), jb = __float_as_int(eb.y);
            // Exact lax.top_k order: smaller distance first; tie -> lower j.
            bool ta = (ea.x < eb.x) || (ea.x == eb.x && ja < jb);
            o[k] = (float)(base + (ta ? ja : jb));
            ia += ta;
            ib += !ta;
        }
    }
}

extern "C" void kernel_launch(void* const* d_in, const int* in_sizes, int n_in,
                              void* d_out, int out_size) {
    // x is the larger input under both elements and bytes conventions.
    int xi = 0;
    for (int i = 1; i < n_in; ++i)
        if (in_sizes[i] > in_sizes[xi]) xi = i;
    const float* x = (const float*)d_in[xi];
    float* out = (float*)d_out;

    dim3 grid(NPTS / QPB);  // 1024 blocks x 128 threads, 7 blocks/SM
    knn_kernel<<<grid, BLOCK>>>(x, out);
}

// round 17
// speedup vs baseline: 1.0462x; 1.0462x over previous
#include <cuda_runtime.h>
#include <math_constants.h>

// Static shape: N=65536, 16 segments of SEG=4096, D=3, K=20.
// Two-kernel plan:
//  k1: 1024 blocks = (512 query-tiles) x (2 candidate halves). Each block
//      scans a contiguous 2048-point half-range for 128 queries, emitting a
//      sorted top-20 partial list per (query, half) into global scratch.
//  k2: one thread per query merges its two sorted lists (exact tie-break).
#define KNN 20
#define NPTS 65536
#define SEG 4096
#define HALF 2048
#define QPB 128
#define BUFCAP 10
#define NPH 13

typedef unsigned long long u64;

// Scratch: partial lists, (distance, index-bits). 2*65536*20*8B = 21 MB.
__device__ float2 g_part[2][NPTS][KNN];

__device__ __forceinline__ u64 pk2(float lo, float hi) {
    u64 r;
    asm("mov.b64 %0, {%1, %2};" : "=l"(r) : "f"(lo), "f"(hi));
    return r;
}
__device__ __forceinline__ void upk2(float& lo, float& hi, u64 v) {
    asm("mov.b64 {%0, %1}, %2;" : "=f"(lo), "=f"(hi) : "l"(v));
}
__device__ __forceinline__ u64 add2(u64 a, u64 b) {
    u64 r;
    asm("add.rn.f32x2 %0, %1, %2;" : "=l"(r) : "l"(a), "l"(b));
    return r;
}
__device__ __forceinline__ u64 mul2(u64 a, u64 b) {
    u64 r;
    asm("mul.rn.f32x2 %0, %1, %2;" : "=l"(r) : "l"(a), "l"(b));
    return r;
}
__device__ __forceinline__ u64 fma2(u64 a, u64 b, u64 c) {
    u64 r;
    asm("fma.rn.f32x2 %0, %1, %2, %3;" : "=l"(r) : "l"(a), "l"(b), "l"(c));
    return r;
}

// Parallel predicated-shift insert into sorted ascending top-K.
// Strict '<' + ascending-j visit order = lax.top_k tie-breaking.
__device__ __forceinline__ void par_insert(float d, int j, float* dist,
                                           int* idx) {
    if (d < dist[KNN - 1]) {
        bool c[KNN];
#pragma unroll
        for (int k = 0; k < KNN; ++k) c[k] = d < dist[k];
#pragma unroll
        for (int k = KNN - 1; k > 0; --k) {
            dist[k] = c[k - 1] ? dist[k - 1] : (c[k] ? d : dist[k]);
            idx[k] = c[k - 1] ? idx[k - 1] : (c[k] ? j : idx[k]);
        }
        if (c[0]) {
            dist[0] = d;
            idx[0] = j;
        }
    }
}

__global__ __launch_bounds__(QPB) void knn_scan_kernel(
    const float* __restrict__ x) {
    __shared__ float xs[HALF], ys[HALF], zs[HALF];
    __shared__ float2 pbuf[BUFCAP * QPB];

    const int tid = threadIdx.x;
    const int half = blockIdx.x & 1;
    const int qt = blockIdx.x >> 1;          // query tile [0, 512)
    const int qg = qt * QPB + tid;           // global query index
    const int base = (qg >> 12) << 12;       // segment base (SEG = 4096)
    const int cbase = base + half * HALF;    // this block's candidate base

    // Key: d_j = xj*(xj+m2x)+yj*(yj+m2y)+zj*(zj+m2z) = |pj|^2 - 2 q.pj
    // (drops per-query constant |q|^2 -> same ordering).
    const float m2x = -2.0f * x[qg * 3 + 0];
    const float m2y = -2.0f * x[qg * 3 + 1];
    const float m2z = -2.0f * x[qg * 3 + 2];
    const u64 m2x2 = pk2(m2x, m2x);
    const u64 m2y2 = pk2(m2y, m2y);
    const u64 m2z2 = pk2(m2z, m2z);

    float dist[KNN];
    int idx[KNN];
#pragma unroll
    for (int k = 0; k < KNN; ++k) {
        dist[k] = CUDART_INF_F;
        idx[k] = 0;
    }

    // Load this block's 2048-point half-range once.
    for (int i = tid; i < HALF; i += QPB) {
        int g = (cbase + i) * 3;
        xs[i] = x[g + 0];
        ys[i] = x[g + 1];
        zs[i] = x[g + 2];
    }
    __syncthreads();

    const float4* __restrict__ xs4 = (const float4*)xs;
    const float4* __restrict__ ys4 = (const float4*)ys;
    const float4* __restrict__ zs4 = (const float4*)zs;

    float thr = CUDART_INF_F;
    int cnt = 0;

#define PUSH(dv, jv)                                                         \
    do {                                                                     \
        if ((dv) < thr) {                                                    \
            if (cnt < BUFCAP) {                                              \
                pbuf[cnt * QPB + tid] =                                      \
                    make_float2((dv), __int_as_float(jv));                   \
                cnt++;                                                       \
            } else {                                                         \
                par_insert((dv), (jv), dist, idx);                           \
            }                                                                \
        }                                                                    \
    } while (0)

    // Doubling drain schedule over the 2048-candidate scan. First two
    // chunks (<=10 items) fill the list to 20 before thr becomes finite.
    constexpr int B[NPH + 1] = {0,   10,  20,  32,  48,   72,   108,
                                164, 248, 372, 560, 840,  1260, 2048};

#pragma unroll
    for (int ph = 0; ph < NPH; ++ph) {
#pragma unroll 2
        for (int t4 = B[ph] / 4; t4 < B[ph + 1] / 4; ++t4) {
            float4 vx = xs4[t4];
            float4 vy = ys4[t4];
            float4 vz = zs4[t4];
            const int j = t4 * 4;  // local index within the half-range

            u64 vx01 = pk2(vx.x, vx.y), vx23 = pk2(vx.z, vx.w);
            u64 vy01 = pk2(vy.x, vy.y), vy23 = pk2(vy.z, vy.w);
            u64 vz01 = pk2(vz.x, vz.y), vz23 = pk2(vz.z, vz.w);

            u64 acc01 = mul2(vx01, add2(vx01, m2x2));
            acc01 = fma2(vy01, add2(vy01, m2y2), acc01);
            acc01 = fma2(vz01, add2(vz01, m2z2), acc01);
            u64 acc23 = mul2(vx23, add2(vx23, m2x2));
            acc23 = fma2(vy23, add2(vy23, m2y2), acc23);
            acc23 = fma2(vz23, add2(vz23, m2z2), acc23);

            float d0, d1, d2, d3;
            upk2(d0, d1, acc01);
            upk2(d2, d3, acc23);

            PUSH(d0, j + 0);
            PUSH(d1, j + 1);
            PUSH(d2, j + 2);
            PUSH(d3, j + 3);
        }

        // Drain buffered items in push (= ascending j) order.
        int mx = __reduce_max_sync(0xffffffffu, cnt);
        for (int t = 0; t < mx; ++t) {
            if (t < cnt) {
                float2 en = pbuf[t * QPB + tid];
                par_insert(en.x, __float_as_int(en.y), dist, idx);
            }
        }
        cnt = 0;
        thr = dist[KNN - 1];
    }
#undef PUSH

    // Emit sorted partial list (global candidate indices).
#pragma unroll
    for (int k = 0; k < KNN; ++k)
        g_part[half][qg][k] =
            make_float2(dist[k], __int_as_float(cbase + idx[k]));
}

__global__ void knn_merge_kernel(float* __restrict__ out) {
    const int qg = blockIdx.x * blockDim.x + threadIdx.x;
    if (qg >= NPTS) return;

    const float2* la = g_part[0][qg];
    const float2* lb = g_part[1][qg];
    float* o = out + (size_t)qg * KNN;

    int ia = 0, ib = 0;
#pragma unroll
    for (int k = 0; k < KNN; ++k) {
        float2 ea = la[ia], eb = lb[ib];
        int ja = __float_as_int(ea.y), jb = __float_as_int(eb.y);
        // Exact lax.top_k order: smaller distance first; tie -> lower j
        // (ja < jb always across halves, so ties take list a).
        bool ta = (ea.x < eb.x) || (ea.x == eb.x && ja < jb);
        o[k] = (float)(ta ? ja : jb);
        ia += ta;
        ib += !ta;
    }
}

extern "C" void kernel_launch(void* const* d_in, const int* in_sizes, int n_in,
                              void* d_out, int out_size) {
    // x is the larger input under both elements and bytes conventions.
    int xi = 0;
    for (int i = 1; i < n_in; ++i)
        if (in_sizes[i] > in_sizes[xi]) xi = i;
    const float* x = (const float*)d_in[xi];
    float* out = (float*)d_out;

    knn_scan_kernel<<<1024, QPB>>>(x);            // 512 tiles x 2 halves
    knn_merge_kernel<<<NPTS / 256, 256>>>(out);   // 2-way merge per query
}